// round 15
// baseline (speedup 1.0000x reference)
#include <cuda_runtime.h>
#include <cuda_bf16.h>
#include <cstdint>

// ---------------------------------------------------------------------------
// DistributedMPNN: 3 message-passing rounds (shared weights) + h2o head.
//
// Edge layer-2 on tensor pipe via baseline mma.sync m16n8k16 bf16.
// Three-term split (48 MMAs/tile):
//   A[32e x 64] = [m1_hi | m1_lo]
//   pass1 (4 k-tiles): B1[k][n] = W2hi[k%32][n]  -> (hi+lo)·Whi
//   pass2 (2 k-tiles): B2[k][n] = W2lo[k][n]     ->  hi·Wlo
// R15: ROWF=36 restored (R14's ROWF=33 broke float4 16B alignment ->
// misaligned-address trap). Kept: edge launch_bounds(256,4) for 32 warps/SM
// (kernel is L1tex-bound at 74.6%), node kernels 2 threads/node.
// ---------------------------------------------------------------------------

#define MAXN 50000

__device__ float g_P[MAXN * 32];     // per-node layer-1 pre-activation (incl. bm1)
__device__ float g_aggr[MAXN * 32];  // scatter-sum accumulator
__device__ float g_x[MAXN * 9];      // current node features
__device__ int   g_is64;             // edge_index dtype flag
// B fragments: slots 0-7 = pass1 (kt*2+half), slots 8-11 = pass2 (kt<2)
__device__ __align__(16) uint4 g_Bfrag[12][32];

__constant__ __align__(16) float cW9[32];  // Wm1 row 9 (edge_attr weights)
__constant__ __align__(16) float cB2[32];  // bm2

// ---------------- helpers ----------------
__device__ __forceinline__ uint32_t smem_u32(const void* p) {
    uint32_t r;
    asm("{ .reg .u64 t; cvta.to.shared.u64 t, %1; cvt.u32.u64 %0, t; }"
        : "=r"(r) : "l"(p));
    return r;
}
// pack {low half = lo, high half = hi} as bf16x2
__device__ __forceinline__ uint32_t pack_bf16x2(float lo, float hi) {
    uint32_t r;
    asm("cvt.rn.satfinite.bf16x2.f32 %0, %1, %2;" : "=r"(r) : "f"(hi), "f"(lo));
    return r;
}
// chunk-swizzled byte offset inside a 32x128B A tile (row r, byte col c<128)
#define AS(r, c) ((uint32_t)((r) * 128 + ((c) ^ (((r) & 7) << 4))))

__device__ __forceinline__ void mma16816(float* c, const uint32_t* a,
                                         uint32_t b0, uint32_t b1) {
    asm volatile(
        "mma.sync.aligned.m16n8k16.row.col.f32.bf16.bf16.f32 "
        "{%0,%1,%2,%3}, {%4,%5,%6,%7}, {%8,%9}, {%0,%1,%2,%3};"
        : "+f"(c[0]), "+f"(c[1]), "+f"(c[2]), "+f"(c[3])
        : "r"(a[0]), "r"(a[1]), "r"(a[2]), "r"(a[3]), "r"(b0), "r"(b1));
}
__device__ __forceinline__ void ldmatrix_x4(uint32_t* r, uint32_t saddr) {
    asm volatile("ldmatrix.sync.aligned.m8n8.x4.shared.b16 {%0,%1,%2,%3}, [%4];"
                 : "=r"(r[0]), "=r"(r[1]), "=r"(r[2]), "=r"(r[3]) : "r"(saddr));
}

// ---------------------------------------------------------------------------
// Init: block 0 detects edge_index dtype, block 1 builds B fragments;
// all blocks: copy x -> g_x, compute P, zero aggr. One thread per (node, j).
// ---------------------------------------------------------------------------
__global__ void init_kernel(const float* __restrict__ x,
                            const float* __restrict__ Wm1,
                            const float* __restrict__ bm1,
                            const float* __restrict__ Wm2,
                            const int* __restrict__ eiw, int N) {
    if (blockIdx.x == 0) {
        __shared__ int nz;
        if (threadIdx.x == 0) nz = 0;
        __syncthreads();
        if (eiw[2 * threadIdx.x + 1] != 0) atomicOr(&nz, 1);
        __syncthreads();
        if (threadIdx.x == 0) g_is64 = (nz == 0) ? 1 : 0;
    }
    if (blockIdx.x == 1) {
        for (int t = threadIdx.x; t < 384; t += blockDim.x) {
            int slot = t >> 5, lane = t & 31;
            int pass = (slot < 8) ? 0 : 1;
            int s = (slot < 8) ? slot : (slot - 8);
            int kt = s >> 1, h = s & 1;
            int k0 = kt * 16 + (lane & 3) * 2;
            int n0 = lane >> 2;
            uint32_t r[4];
#pragma unroll
            for (int ntl = 0; ntl < 2; ntl++) {
                int n = (2 * h + ntl) * 8 + n0;
#pragma unroll
                for (int kb = 0; kb < 2; kb++) {
                    float v[2];
#pragma unroll
                    for (int j = 0; j < 2; j++) {
                        int k = (k0 + 8 * kb + j) & 31;
                        float w = Wm2[k * 32 + n];
                        float hi = __bfloat162float(__float2bfloat16(w));
                        v[j] = (pass == 0) ? hi : (w - hi);
                    }
                    r[2 * ntl + kb] = pack_bf16x2(v[0], v[1]);
                }
            }
            g_Bfrag[slot][lane] = make_uint4(r[0], r[1], r[2], r[3]);
        }
    }
    int idx = blockIdx.x * blockDim.x + threadIdx.x;
    int n = idx >> 5, j = idx & 31;
    if (n >= N) return;
    float s = bm1[j];
#pragma unroll
    for (int c = 0; c < 9; c++) s = fmaf(x[n * 9 + c], Wm1[c * 32 + j], s);
    g_P[idx] = s;
    g_aggr[idx] = 0.f;
    if (j < 9) g_x[n * 9 + j] = x[n * 9 + j];
}

// ---------------------------------------------------------------------------
// Edge kernel: each warp owns 32 edges. ROWF=36 (144B rows, 16B-aligned).
// ---------------------------------------------------------------------------
#define ROWF 36

__global__ void __launch_bounds__(256, 4)
edge_kernel(const void* __restrict__ eiv, const float* __restrict__ ea, int E) {
    __shared__ __align__(128) float sbuf[8][32 * ROWF];
    __shared__ __align__(16) uint4 sB[12][32];
    const unsigned FULL = 0xffffffffu;
    int lane = threadIdx.x & 31;
    int wid = threadIdx.x >> 5;
    float* buf = sbuf[wid];
    char* Ab = (char*)buf;
    uint32_t sA = smem_u32(buf);
    long long wbase = ((long long)blockIdx.x * 8 + wid) * 32;
    int e = (int)(wbase + lane);
    bool valid = (wbase + lane) < E;

    // stage B fragments once per CTA
    for (int i = threadIdx.x; i < 384; i += 256)
        sB[i >> 5][i & 31] = g_Bfrag[i >> 5][i & 31];
    __syncthreads();

    int src = 0, dst = 0;
    float a = 0.f;
    if (valid) {
        if (g_is64) {
            const long long* ei = (const long long*)eiv;
            src = (int)ei[e];
            dst = (int)ei[(size_t)E + e];
        } else {
            const int* ei = (const int*)eiv;
            src = ei[e];
            dst = ei[(size_t)E + e];
        }
        a = ea[e];
    }

    // ---- Phase 1: float4 cooperative gather (1 line per edge) ----
    {
        int sub = lane & 7;  // 16B chunk within the 128B row
#pragma unroll
        for (int s4 = 0; s4 < 8; s4++) {
            int slot = s4 * 4 + (lane >> 3);
            int sS = __shfl_sync(FULL, src, slot);
            float4 v = *(const float4*)(g_P + (size_t)sS * 32 + 4 * sub);
            *(float4*)(buf + slot * ROWF + 4 * sub) = v;
        }
    }
    __syncwarp();

    // ---- Phase 2: m1 into regs, then split-bf16 A tile (swizzled) ----
    float m[32];
#pragma unroll
    for (int q = 0; q < 8; q++) {
        float4 p = *(const float4*)(buf + lane * ROWF + 4 * q);
        float4 w9 = *(const float4*)(cW9 + 4 * q);
        m[4 * q + 0] = fmaxf(fmaf(a, w9.x, p.x), 0.f);
        m[4 * q + 1] = fmaxf(fmaf(a, w9.y, p.y), 0.f);
        m[4 * q + 2] = fmaxf(fmaf(a, w9.z, p.z), 0.f);
        m[4 * q + 3] = fmaxf(fmaf(a, w9.w, p.w), 0.f);
    }
    __syncwarp();  // all P reads done before A overwrites the buffer
    uint32_t sw = (uint32_t)((lane & 7) << 4);
#pragma unroll
    for (int q = 0; q < 4; q++) {
        uint4 hi4, lo4;
        uint32_t* hi = (uint32_t*)&hi4;
        uint32_t* lo = (uint32_t*)&lo4;
#pragma unroll
        for (int i = 0; i < 4; i++) {
            float m0 = m[8 * q + 2 * i], m1v = m[8 * q + 2 * i + 1];
            uint32_t hp = pack_bf16x2(m0, m1v);
            float h0 = __uint_as_float(hp << 16);
            float h1 = __uint_as_float(hp & 0xFFFF0000u);
            lo[i] = pack_bf16x2(m0 - h0, m1v - h1);
            hi[i] = hp;
        }
        *(uint4*)(Ab + lane * 128 + ((16 * q) ^ sw)) = hi4;        // k [0:32)
        *(uint4*)(Ab + lane * 128 + ((64 + 16 * q) ^ sw)) = lo4;   // k [32:64)
    }
    __syncwarp();

    // ---- Phase 3: ldmatrix once per k-tile + 3-term MMA ----
    float c[32];  // [mt][nt] -> c[(mt*4+nt)*4 .. +3]
#pragma unroll
    for (int i = 0; i < 32; i++) c[i] = 0.f;

    uint32_t lrow = (uint32_t)(lane & 15);
    uint32_t lcol = (uint32_t)((lane >> 4) * 16);
#pragma unroll
    for (int kt = 0; kt < 4; kt++) {
        uint32_t a0[4], a1[4];
        uint32_t cb = (uint32_t)kt * 32 + lcol;
        ldmatrix_x4(a0, sA + AS(lrow, cb));        // rows 0-15
        ldmatrix_x4(a1, sA + AS(16 + lrow, cb));   // rows 16-31
        {   // pass1: Whi (duplicated halves)
            uint4 Ba = sB[kt * 2][lane];
            uint4 Bb = sB[kt * 2 + 1][lane];
            mma16816(c + 0,  a0, Ba.x, Ba.y);
            mma16816(c + 4,  a0, Ba.z, Ba.w);
            mma16816(c + 8,  a0, Bb.x, Bb.y);
            mma16816(c + 12, a0, Bb.z, Bb.w);
            mma16816(c + 16, a1, Ba.x, Ba.y);
            mma16816(c + 20, a1, Ba.z, Ba.w);
            mma16816(c + 24, a1, Bb.x, Bb.y);
            mma16816(c + 28, a1, Bb.z, Bb.w);
        }
        if (kt < 2) {  // pass2: hi · Wlo (A hi columns only)
            uint4 Ca = sB[8 + kt * 2][lane];
            uint4 Cb = sB[8 + kt * 2 + 1][lane];
            mma16816(c + 0,  a0, Ca.x, Ca.y);
            mma16816(c + 4,  a0, Ca.z, Ca.w);
            mma16816(c + 8,  a0, Cb.x, Cb.y);
            mma16816(c + 12, a0, Cb.z, Cb.w);
            mma16816(c + 16, a1, Ca.x, Ca.y);
            mma16816(c + 20, a1, Ca.z, Ca.w);
            mma16816(c + 24, a1, Cb.x, Cb.y);
            mma16816(c + 28, a1, Cb.z, Cb.w);
        }
    }
    __syncwarp();  // all ldmatrix reads done before C overwrites the buffer

    // ---- Phase 4: bias + relu -> smem rows, cooperative scatter ----
#pragma unroll
    for (int nt = 0; nt < 4; nt++) {
        int col = nt * 8 + (lane & 3) * 2;
        float b0 = cB2[col], b1 = cB2[col + 1];
#pragma unroll
        for (int mt = 0; mt < 2; mt++) {
            const float* cc = c + (mt * 4 + nt) * 4;
            int row0 = mt * 16 + (lane >> 2);
            float2 v0, v1;
            v0.x = fmaxf(cc[0] + b0, 0.f);
            v0.y = fmaxf(cc[1] + b1, 0.f);
            v1.x = fmaxf(cc[2] + b0, 0.f);
            v1.y = fmaxf(cc[3] + b1, 0.f);
            *(float2*)(buf + row0 * ROWF + col) = v0;
            *(float2*)(buf + (row0 + 8) * ROWF + col) = v1;
        }
    }
    __syncwarp();

    int g = lane >> 3, sub = lane & 7;
#pragma unroll
    for (int i = 0; i < 8; i++) {
        int slot = 4 * i + g;
        int dS = __shfl_sync(FULL, dst, slot);
        bool vS = (wbase + slot) < E;
        float4 v = *(const float4*)(buf + slot * ROWF + 4 * sub);
        if (vS) {
            size_t ga = __cvta_generic_to_global(
                (void*)(g_aggr + (size_t)dS * 32 + 4 * sub));
            asm volatile("red.global.add.v4.f32 [%0], {%1, %2, %3, %4};"
                         :: "l"((unsigned long long)ga),
                            "f"(v.x), "f"(v.y), "f"(v.z), "f"(v.w)
                         : "memory");
        }
    }
}

// ---------------------------------------------------------------------------
// Node update (rounds 0,1): TWO threads per node (h = half). Each computes
// u1[8h..8h+8) over all 41 inputs (aggr streamed), exchanges u1 via shfl,
// both compute full u2, each writes its 16-col half of P and zeroes aggr.
// All lanes stay active (clamp + predicated stores) so shfl masks are safe.
// ---------------------------------------------------------------------------
__global__ void __launch_bounds__(128, 8)
update_kernel(const float* __restrict__ Wu1, const float* __restrict__ bu1,
              const float* __restrict__ Wu2, const float* __restrict__ bu2,
              const float* __restrict__ Wm1, const float* __restrict__ bm1,
              int N) {
    __shared__ float sWu1[656], sWu2[128], sWm1[288];
    __shared__ float sbu1[16], sbu2[8], sbm1[32];
    for (int i = threadIdx.x; i < 656; i += blockDim.x) sWu1[i] = Wu1[i];
    for (int i = threadIdx.x; i < 128; i += blockDim.x) sWu2[i] = Wu2[i];
    for (int i = threadIdx.x; i < 288; i += blockDim.x) sWm1[i] = Wm1[i];
    if (threadIdx.x < 16) sbu1[threadIdx.x] = bu1[threadIdx.x];
    if (threadIdx.x < 8)  sbu2[threadIdx.x] = bu2[threadIdx.x];
    if (threadIdx.x < 32) sbm1[threadIdx.x] = bm1[threadIdx.x];
    __syncthreads();

    const unsigned FULL = 0xffffffffu;
    int t = blockIdx.x * blockDim.x + threadIdx.x;
    int n = t >> 1, h = t & 1;
    bool ok = n < N;
    int nc = ok ? n : (N - 1);

    float xv[9];
#pragma unroll
    for (int c = 0; c < 9; c++) xv[c] = g_x[nc * 9 + c];

    // u1 half: outputs i in [8h, 8h+8), all 41 inputs (aggr streamed)
    float u1[8];
#pragma unroll
    for (int i = 0; i < 8; i++) u1[i] = sbu1[8 * h + i];
#pragma unroll
    for (int c = 0; c < 9; c++) {
        float xc = xv[c];
#pragma unroll
        for (int i = 0; i < 8; i++) u1[i] = fmaf(xc, sWu1[c * 16 + 8 * h + i], u1[i]);
    }
    float4* ar = (float4*)(g_aggr + (size_t)nc * 32);
#pragma unroll
    for (int q = 0; q < 8; q++) {
        float4 tq = ar[q];
        const float* w0 = sWu1 + (9 + 4 * q) * 16 + 8 * h;
#pragma unroll
        for (int i = 0; i < 8; i++) {
            float s = u1[i];
            s = fmaf(tq.x, w0[i], s);
            s = fmaf(tq.y, w0[16 + i], s);
            s = fmaf(tq.z, w0[32 + i], s);
            s = fmaf(tq.w, w0[48 + i], s);
            u1[i] = s;
        }
    }
#pragma unroll
    for (int i = 0; i < 8; i++) u1[i] = fmaxf(u1[i], 0.f);

    // u2 full (both threads): own half + partner half via shfl
    float u2[8];
#pragma unroll
    for (int j = 0; j < 8; j++) u2[j] = sbu2[j];
#pragma unroll
    for (int i = 0; i < 8; i++) {
        float ui = u1[i];
        const float* w = sWu2 + (8 * h + i) * 8;
#pragma unroll
        for (int j = 0; j < 8; j++) u2[j] = fmaf(ui, w[j], u2[j]);
    }
#pragma unroll
    for (int i = 0; i < 8; i++) {
        float up = __shfl_xor_sync(FULL, u1[i], 1);
        const float* w = sWu2 + (8 * (h ^ 1) + i) * 8;
#pragma unroll
        for (int j = 0; j < 8; j++) u2[j] = fmaf(up, w[j], u2[j]);
    }
#pragma unroll
    for (int j = 0; j < 8; j++) u2[j] = fmaxf(u2[j], 0.f);

    float nx[9];
    nx[0] = xv[0];
#pragma unroll
    for (int j = 0; j < 8; j++) nx[1 + j] = u2[j];
    if (ok && h == 0) {
#pragma unroll
        for (int c = 0; c < 9; c++) g_x[n * 9 + c] = nx[c];
    }

    // P half: cols [16h, 16h+16)
    float p[16];
#pragma unroll
    for (int j = 0; j < 16; j++) p[j] = sbm1[16 * h + j];
#pragma unroll
    for (int c = 0; c < 9; c++) {
        float xc = nx[c];
        const float* w = sWm1 + c * 32 + 16 * h;
#pragma unroll
        for (int j = 0; j < 16; j++) p[j] = fmaf(xc, w[j], p[j]);
    }
    if (ok) {
        float4* Pr = (float4*)(g_P + (size_t)n * 32 + 16 * h);
        float4* Az = (float4*)(g_aggr + (size_t)n * 32 + 16 * h);
        float4 z4 = make_float4(0.f, 0.f, 0.f, 0.f);
#pragma unroll
        for (int q = 0; q < 4; q++) {
            Pr[q] = make_float4(p[4 * q], p[4 * q + 1], p[4 * q + 2], p[4 * q + 3]);
            Az[q] = z4;
        }
    }
}

// ---------------------------------------------------------------------------
// Final round: update MLP fused with h2o head, two threads per node.
// ---------------------------------------------------------------------------
__global__ void __launch_bounds__(128, 8)
final_kernel(const float* __restrict__ Wu1, const float* __restrict__ bu1,
             const float* __restrict__ Wu2, const float* __restrict__ bu2,
             const float* __restrict__ Wh1, const float* __restrict__ bh1,
             const float* __restrict__ Wh2, const float* __restrict__ bh2,
             float* __restrict__ out, int N) {
    __shared__ float sWu1[656], sWu2[128], sWh1[128], sWh2[16];
    __shared__ float sbu1[16], sbu2[8], sbh1[16], sbh2;
    for (int i = threadIdx.x; i < 656; i += blockDim.x) sWu1[i] = Wu1[i];
    for (int i = threadIdx.x; i < 128; i += blockDim.x) sWu2[i] = Wu2[i];
    for (int i = threadIdx.x; i < 128; i += blockDim.x) sWh1[i] = Wh1[i];
    if (threadIdx.x < 16) { sWh2[threadIdx.x] = Wh2[threadIdx.x]; sbu1[threadIdx.x] = bu1[threadIdx.x]; sbh1[threadIdx.x] = bh1[threadIdx.x]; }
    if (threadIdx.x < 8)  sbu2[threadIdx.x] = bu2[threadIdx.x];
    if (threadIdx.x == 0) sbh2 = bh2[0];
    __syncthreads();

    const unsigned FULL = 0xffffffffu;
    int t = blockIdx.x * blockDim.x + threadIdx.x;
    int n = t >> 1, h = t & 1;
    bool ok = n < N;
    int nc = ok ? n : (N - 1);

    float xv[9];
#pragma unroll
    for (int c = 0; c < 9; c++) xv[c] = g_x[nc * 9 + c];

    float u1[8];
#pragma unroll
    for (int i = 0; i < 8; i++) u1[i] = sbu1[8 * h + i];
#pragma unroll
    for (int c = 0; c < 9; c++) {
        float xc = xv[c];
#pragma unroll
        for (int i = 0; i < 8; i++) u1[i] = fmaf(xc, sWu1[c * 16 + 8 * h + i], u1[i]);
    }
    const float4* ar = (const float4*)(g_aggr + (size_t)nc * 32);
#pragma unroll
    for (int q = 0; q < 8; q++) {
        float4 tq = ar[q];
        const float* w0 = sWu1 + (9 + 4 * q) * 16 + 8 * h;
#pragma unroll
        for (int i = 0; i < 8; i++) {
            float s = u1[i];
            s = fmaf(tq.x, w0[i], s);
            s = fmaf(tq.y, w0[16 + i], s);
            s = fmaf(tq.z, w0[32 + i], s);
            s = fmaf(tq.w, w0[48 + i], s);
            u1[i] = s;
        }
    }
#pragma unroll
    for (int i = 0; i < 8; i++) u1[i] = fmaxf(u1[i], 0.f);

    float u2[8];
#pragma unroll
    for (int j = 0; j < 8; j++) u2[j] = sbu2[j];
#pragma unroll
    for (int i = 0; i < 8; i++) {
        float ui = u1[i];
        const float* w = sWu2 + (8 * h + i) * 8;
#pragma unroll
        for (int j = 0; j < 8; j++) u2[j] = fmaf(ui, w[j], u2[j]);
    }
#pragma unroll
    for (int i = 0; i < 8; i++) {
        float up = __shfl_xor_sync(FULL, u1[i], 1);
        const float* w = sWu2 + (8 * (h ^ 1) + i) * 8;
#pragma unroll
        for (int j = 0; j < 8; j++) u2[j] = fmaf(up, w[j], u2[j]);
    }
#pragma unroll
    for (int j = 0; j < 8; j++) u2[j] = fmaxf(u2[j], 0.f);

    // h2o: o half [8h, 8h+8), partial z, combine via shfl
    float o[8];
#pragma unroll
    for (int i = 0; i < 8; i++) o[i] = sbh1[8 * h + i];
#pragma unroll
    for (int c = 0; c < 8; c++) {
        float uc = u2[c];
#pragma unroll
        for (int i = 0; i < 8; i++) o[i] = fmaf(uc, sWh1[c * 16 + 8 * h + i], o[i]);
    }
    float z = 0.f;
#pragma unroll
    for (int i = 0; i < 8; i++) z = fmaf(fmaxf(o[i], 0.f), sWh2[8 * h + i], z);
    z += __shfl_xor_sync(FULL, z, 1);
    if (ok && h == 0)
        out[n] = 1.f / (1.f + __expf(-(z + sbh2)));
}

// ---------------------------------------------------------------------------
extern "C" void kernel_launch(void* const* d_in, const int* in_sizes, int n_in,
                              void* d_out, int out_size) {
    const float* x   = (const float*)d_in[0];
    const void*  ei  = d_in[1];
    const float* ea  = (const float*)d_in[2];
    const float* Wm1 = (const float*)d_in[3];
    const float* bm1 = (const float*)d_in[4];
    const float* Wm2 = (const float*)d_in[5];
    const float* bm2 = (const float*)d_in[6];
    const float* Wu1 = (const float*)d_in[7];
    const float* bu1 = (const float*)d_in[8];
    const float* Wu2 = (const float*)d_in[9];
    const float* bu2 = (const float*)d_in[10];
    const float* Wh1 = (const float*)d_in[11];
    const float* bh1 = (const float*)d_in[12];
    const float* Wh2 = (const float*)d_in[13];
    const float* bh2 = (const float*)d_in[14];
    float* out = (float*)d_out;

    int N = in_sizes[0] / 9;
    int E = in_sizes[2];  // edge_attr is [E, 1]
    int ngrid = (2 * N + 127) / 128;

    cudaMemcpyToSymbolAsync(cW9, (const char*)Wm1 + 9 * 32 * sizeof(float),
                            32 * sizeof(float), 0, cudaMemcpyDeviceToDevice, 0);
    cudaMemcpyToSymbolAsync(cB2, bm2, 32 * sizeof(float), 0,
                            cudaMemcpyDeviceToDevice, 0);

    init_kernel<<<(N * 32 + 255) / 256, 256>>>(x, Wm1, bm1, Wm2, (const int*)ei, N);
    for (int r = 0; r < 3; r++) {
        edge_kernel<<<(E + 255) / 256, 256>>>(ei, ea, E);
        if (r < 2)
            update_kernel<<<ngrid, 128>>>(Wu1, bu1, Wu2, bu2, Wm1, bm1, N);
        else
            final_kernel<<<ngrid, 128>>>(Wu1, bu1, Wu2, bu2,
                                         Wh1, bh1, Wh2, bh2, out, N);
    }
}

// round 16
// speedup vs baseline: 1.1663x; 1.1663x over previous
#include <cuda_runtime.h>
#include <cuda_bf16.h>
#include <cstdint>

// ---------------------------------------------------------------------------
// DistributedMPNN: 3 message-passing rounds (shared weights) + h2o head.
//
// Edge layer-2 on tensor pipe via baseline mma.sync m16n8k16 bf16,
// three-term split (48 MMAs / 32-edge tile):
//   A[32e x 64] = [m1_hi | m1_lo]
//   pass1 (4 k-tiles): B1[k][n] = W2hi[k%32][n]  -> (hi+lo)·Whi
//   pass2 (2 k-tiles): B2[k][n] = W2lo[k][n]     ->  hi·Wlo
//
// R16: fused gather->m1->split->A-store. The kernel is L1tex-THROUGHPUT
// bound (R15: more warps raised L1 to 86% but slowed it down). m1 is now
// computed in gather layout (a_slot via shfl) and written straight into the
// swizzled A tile (pair-exchange shfl + STS.128), deleting the gather-STS
// and LDS-readback stages: 256 -> 192 wavefronts per warp-tile (-25% L1).
// Numerics identical to R13/R15. Edge back to 3 CTAs/SM (reg-cap spills
// hurt in R15). Node kernels keep the 2-thread-per-node split.
// ---------------------------------------------------------------------------

#define MAXN 50000

__device__ float g_P[MAXN * 32];     // per-node layer-1 pre-activation (incl. bm1)
__device__ float g_aggr[MAXN * 32];  // scatter-sum accumulator
__device__ float g_x[MAXN * 9];      // current node features
__device__ int   g_is64;             // edge_index dtype flag
// B fragments: slots 0-7 = pass1 (kt*2+half), slots 8-11 = pass2 (kt<2)
__device__ __align__(16) uint4 g_Bfrag[12][32];

__constant__ __align__(16) float cW9[32];  // Wm1 row 9 (edge_attr weights)
__constant__ __align__(16) float cB2[32];  // bm2

// ---------------- helpers ----------------
__device__ __forceinline__ uint32_t smem_u32(const void* p) {
    uint32_t r;
    asm("{ .reg .u64 t; cvta.to.shared.u64 t, %1; cvt.u32.u64 %0, t; }"
        : "=r"(r) : "l"(p));
    return r;
}
// pack {low half = lo, high half = hi} as bf16x2
__device__ __forceinline__ uint32_t pack_bf16x2(float lo, float hi) {
    uint32_t r;
    asm("cvt.rn.satfinite.bf16x2.f32 %0, %1, %2;" : "=r"(r) : "f"(hi), "f"(lo));
    return r;
}
// chunk-swizzled byte offset inside a 32x128B A tile (row r, byte col c<128)
#define AS(r, c) ((uint32_t)((r) * 128 + ((c) ^ (((r) & 7) << 4))))

__device__ __forceinline__ void mma16816(float* c, const uint32_t* a,
                                         uint32_t b0, uint32_t b1) {
    asm volatile(
        "mma.sync.aligned.m16n8k16.row.col.f32.bf16.bf16.f32 "
        "{%0,%1,%2,%3}, {%4,%5,%6,%7}, {%8,%9}, {%0,%1,%2,%3};"
        : "+f"(c[0]), "+f"(c[1]), "+f"(c[2]), "+f"(c[3])
        : "r"(a[0]), "r"(a[1]), "r"(a[2]), "r"(a[3]), "r"(b0), "r"(b1));
}
__device__ __forceinline__ void ldmatrix_x4(uint32_t* r, uint32_t saddr) {
    asm volatile("ldmatrix.sync.aligned.m8n8.x4.shared.b16 {%0,%1,%2,%3}, [%4];"
                 : "=r"(r[0]), "=r"(r[1]), "=r"(r[2]), "=r"(r[3]) : "r"(saddr));
}

// ---------------------------------------------------------------------------
// Init: block 0 detects edge_index dtype, block 1 builds B fragments;
// all blocks: copy x -> g_x, compute P, zero aggr. One thread per (node, j).
// ---------------------------------------------------------------------------
__global__ void init_kernel(const float* __restrict__ x,
                            const float* __restrict__ Wm1,
                            const float* __restrict__ bm1,
                            const float* __restrict__ Wm2,
                            const int* __restrict__ eiw, int N) {
    if (blockIdx.x == 0) {
        __shared__ int nz;
        if (threadIdx.x == 0) nz = 0;
        __syncthreads();
        if (eiw[2 * threadIdx.x + 1] != 0) atomicOr(&nz, 1);
        __syncthreads();
        if (threadIdx.x == 0) g_is64 = (nz == 0) ? 1 : 0;
    }
    if (blockIdx.x == 1) {
        for (int t = threadIdx.x; t < 384; t += blockDim.x) {
            int slot = t >> 5, lane = t & 31;
            int pass = (slot < 8) ? 0 : 1;
            int s = (slot < 8) ? slot : (slot - 8);
            int kt = s >> 1, h = s & 1;
            int k0 = kt * 16 + (lane & 3) * 2;
            int n0 = lane >> 2;
            uint32_t r[4];
#pragma unroll
            for (int ntl = 0; ntl < 2; ntl++) {
                int n = (2 * h + ntl) * 8 + n0;
#pragma unroll
                for (int kb = 0; kb < 2; kb++) {
                    float v[2];
#pragma unroll
                    for (int j = 0; j < 2; j++) {
                        int k = (k0 + 8 * kb + j) & 31;
                        float w = Wm2[k * 32 + n];
                        float hi = __bfloat162float(__float2bfloat16(w));
                        v[j] = (pass == 0) ? hi : (w - hi);
                    }
                    r[2 * ntl + kb] = pack_bf16x2(v[0], v[1]);
                }
            }
            g_Bfrag[slot][lane] = make_uint4(r[0], r[1], r[2], r[3]);
        }
    }
    int idx = blockIdx.x * blockDim.x + threadIdx.x;
    int n = idx >> 5, j = idx & 31;
    if (n >= N) return;
    float s = bm1[j];
#pragma unroll
    for (int c = 0; c < 9; c++) s = fmaf(x[n * 9 + c], Wm1[c * 32 + j], s);
    g_P[idx] = s;
    g_aggr[idx] = 0.f;
    if (j < 9) g_x[n * 9 + j] = x[n * 9 + j];
}

// ---------------------------------------------------------------------------
// Edge kernel: each warp owns 32 edges.
//   1) FUSED gather+compute+store: step covers rows 4i+g; lane (g,sub) loads
//      P[src_slot][4sub..+3] (1 line/edge), computes m1 = relu(P + a*W9),
//      splits to bf16 hi/lo, pair-exchanges (shfl_xor 1) and writes 16B of
//      the swizzled A tile (even lane: hi, odd lane: lo) via one STS.128.
//   2) ldmatrix.x4 + 48 mma.sync (3-term split)
//   3) bias+relu -> smem rows; coop scatter red.global.add.v4 (1 line/edge)
// ---------------------------------------------------------------------------
#define ROWF 36

__global__ void __launch_bounds__(256, 3)
edge_kernel(const void* __restrict__ eiv, const float* __restrict__ ea, int E) {
    __shared__ __align__(128) float sbuf[8][32 * ROWF];
    __shared__ __align__(16) uint4 sB[12][32];
    const unsigned FULL = 0xffffffffu;
    int lane = threadIdx.x & 31;
    int wid = threadIdx.x >> 5;
    float* buf = sbuf[wid];
    char* Ab = (char*)buf;            // A tile: first 4096B, 128B rows
    uint32_t sA = smem_u32(buf);
    long long wbase = ((long long)blockIdx.x * 8 + wid) * 32;
    int e = (int)(wbase + lane);
    bool valid = (wbase + lane) < E;

    // stage B fragments once per CTA
    for (int i = threadIdx.x; i < 384; i += 256)
        sB[i >> 5][i & 31] = g_Bfrag[i >> 5][i & 31];
    __syncthreads();

    int src = 0, dst = 0;
    float a = 0.f;
    if (valid) {
        if (g_is64) {
            const long long* ei = (const long long*)eiv;
            src = (int)ei[e];
            dst = (int)ei[(size_t)E + e];
        } else {
            const int* ei = (const int*)eiv;
            src = ei[e];
            dst = ei[(size_t)E + e];
        }
        a = ea[e];
    }

    int g = lane >> 3, sub = lane & 7;

    // ---- Phase 1 (fused): gather -> m1 -> split -> A tile ----
    {
        int j = sub >> 1;
        int odd = sub & 1;
        uint32_t coff = (odd ? 64u : 0u) + 16u * (uint32_t)j;
        float4 w9 = *(const float4*)(cW9 + 4 * sub);
#pragma unroll
        for (int i = 0; i < 8; i++) {
            int slot = 4 * i + g;
            int sS = __shfl_sync(FULL, src, slot);
            float aS = __shfl_sync(FULL, a, slot);
            float4 v = *(const float4*)(g_P + (size_t)sS * 32 + 4 * sub);
            float m0 = fmaxf(fmaf(aS, w9.x, v.x), 0.f);
            float m1v = fmaxf(fmaf(aS, w9.y, v.y), 0.f);
            float m2 = fmaxf(fmaf(aS, w9.z, v.z), 0.f);
            float m3 = fmaxf(fmaf(aS, w9.w, v.w), 0.f);
            uint32_t hw0 = pack_bf16x2(m0, m1v);
            uint32_t hw1 = pack_bf16x2(m2, m3);
            float h0 = __uint_as_float(hw0 << 16);
            float h1 = __uint_as_float(hw0 & 0xFFFF0000u);
            float h2 = __uint_as_float(hw1 << 16);
            float h3 = __uint_as_float(hw1 & 0xFFFF0000u);
            uint32_t lw0 = pack_bf16x2(m0 - h0, m1v - h1);
            uint32_t lw1 = pack_bf16x2(m2 - h2, m3 - h3);
            uint32_t xh0 = __shfl_xor_sync(FULL, hw0, 1);
            uint32_t xh1 = __shfl_xor_sync(FULL, hw1, 1);
            uint32_t xl0 = __shfl_xor_sync(FULL, lw0, 1);
            uint32_t xl1 = __shfl_xor_sync(FULL, lw1, 1);
            uint4 val;
            if (!odd) val = make_uint4(hw0, hw1, xh0, xh1);   // hi cols 8j..8j+7
            else      val = make_uint4(xl0, xl1, lw0, lw1);   // lo cols 8j..8j+7
            *(uint4*)(Ab + AS(slot, coff)) = val;
        }
    }
    __syncwarp();

    // ---- Phase 2: ldmatrix once per k-tile + 3-term MMA ----
    float c[32];  // [mt][nt] -> c[(mt*4+nt)*4 .. +3]
#pragma unroll
    for (int i = 0; i < 32; i++) c[i] = 0.f;

    uint32_t lrow = (uint32_t)(lane & 15);
    uint32_t lcol = (uint32_t)((lane >> 4) * 16);
#pragma unroll
    for (int kt = 0; kt < 4; kt++) {
        uint32_t a0[4], a1[4];
        uint32_t cb = (uint32_t)kt * 32 + lcol;
        ldmatrix_x4(a0, sA + AS(lrow, cb));        // rows 0-15
        ldmatrix_x4(a1, sA + AS(16 + lrow, cb));   // rows 16-31
        {   // pass1: Whi (duplicated halves)
            uint4 Ba = sB[kt * 2][lane];
            uint4 Bb = sB[kt * 2 + 1][lane];
            mma16816(c + 0,  a0, Ba.x, Ba.y);
            mma16816(c + 4,  a0, Ba.z, Ba.w);
            mma16816(c + 8,  a0, Bb.x, Bb.y);
            mma16816(c + 12, a0, Bb.z, Bb.w);
            mma16816(c + 16, a1, Ba.x, Ba.y);
            mma16816(c + 20, a1, Ba.z, Ba.w);
            mma16816(c + 24, a1, Bb.x, Bb.y);
            mma16816(c + 28, a1, Bb.z, Bb.w);
        }
        if (kt < 2) {  // pass2: hi · Wlo (A hi columns only)
            uint4 Ca = sB[8 + kt * 2][lane];
            uint4 Cb = sB[8 + kt * 2 + 1][lane];
            mma16816(c + 0,  a0, Ca.x, Ca.y);
            mma16816(c + 4,  a0, Ca.z, Ca.w);
            mma16816(c + 8,  a0, Cb.x, Cb.y);
            mma16816(c + 12, a0, Cb.z, Cb.w);
            mma16816(c + 16, a1, Ca.x, Ca.y);
            mma16816(c + 20, a1, Ca.z, Ca.w);
            mma16816(c + 24, a1, Cb.x, Cb.y);
            mma16816(c + 28, a1, Cb.z, Cb.w);
        }
    }
    __syncwarp();  // all ldmatrix reads done before epi overwrites the buffer

    // ---- Phase 3: bias + relu -> smem rows, cooperative scatter ----
#pragma unroll
    for (int nt = 0; nt < 4; nt++) {
        int col = nt * 8 + (lane & 3) * 2;
        float b0 = cB2[col], b1 = cB2[col + 1];
#pragma unroll
        for (int mt = 0; mt < 2; mt++) {
            const float* cc = c + (mt * 4 + nt) * 4;
            int row0 = mt * 16 + (lane >> 2);
            float2 v0, v1;
            v0.x = fmaxf(cc[0] + b0, 0.f);
            v0.y = fmaxf(cc[1] + b1, 0.f);
            v1.x = fmaxf(cc[2] + b0, 0.f);
            v1.y = fmaxf(cc[3] + b1, 0.f);
            *(float2*)(buf + row0 * ROWF + col) = v0;
            *(float2*)(buf + (row0 + 8) * ROWF + col) = v1;
        }
    }
    __syncwarp();

    {
        int sg = lane >> 3, ssub = lane & 7;
#pragma unroll
        for (int i = 0; i < 8; i++) {
            int slot = 4 * i + sg;
            int dS = __shfl_sync(FULL, dst, slot);
            bool vS = (wbase + slot) < E;
            float4 v = *(const float4*)(buf + slot * ROWF + 4 * ssub);
            if (vS) {
                size_t ga = __cvta_generic_to_global(
                    (void*)(g_aggr + (size_t)dS * 32 + 4 * ssub));
                asm volatile("red.global.add.v4.f32 [%0], {%1, %2, %3, %4};"
                             :: "l"((unsigned long long)ga),
                                "f"(v.x), "f"(v.y), "f"(v.z), "f"(v.w)
                             : "memory");
            }
        }
    }
}

// ---------------------------------------------------------------------------
// Node update (rounds 0,1): TWO threads per node (h = half). Each computes
// u1[8h..8h+8) over all 41 inputs (aggr streamed), exchanges u1 via shfl,
// both compute full u2, each writes its 16-col half of P and zeroes aggr.
// ---------------------------------------------------------------------------
__global__ void __launch_bounds__(128, 8)
update_kernel(const float* __restrict__ Wu1, const float* __restrict__ bu1,
              const float* __restrict__ Wu2, const float* __restrict__ bu2,
              const float* __restrict__ Wm1, const float* __restrict__ bm1,
              int N) {
    __shared__ float sWu1[656], sWu2[128], sWm1[288];
    __shared__ float sbu1[16], sbu2[8], sbm1[32];
    for (int i = threadIdx.x; i < 656; i += blockDim.x) sWu1[i] = Wu1[i];
    for (int i = threadIdx.x; i < 128; i += blockDim.x) sWu2[i] = Wu2[i];
    for (int i = threadIdx.x; i < 288; i += blockDim.x) sWm1[i] = Wm1[i];
    if (threadIdx.x < 16) sbu1[threadIdx.x] = bu1[threadIdx.x];
    if (threadIdx.x < 8)  sbu2[threadIdx.x] = bu2[threadIdx.x];
    if (threadIdx.x < 32) sbm1[threadIdx.x] = bm1[threadIdx.x];
    __syncthreads();

    const unsigned FULL = 0xffffffffu;
    int t = blockIdx.x * blockDim.x + threadIdx.x;
    int n = t >> 1, h = t & 1;
    bool ok = n < N;
    int nc = ok ? n : (N - 1);

    float xv[9];
#pragma unroll
    for (int c = 0; c < 9; c++) xv[c] = g_x[nc * 9 + c];

    float u1[8];
#pragma unroll
    for (int i = 0; i < 8; i++) u1[i] = sbu1[8 * h + i];
#pragma unroll
    for (int c = 0; c < 9; c++) {
        float xc = xv[c];
#pragma unroll
        for (int i = 0; i < 8; i++) u1[i] = fmaf(xc, sWu1[c * 16 + 8 * h + i], u1[i]);
    }
    float4* ar = (float4*)(g_aggr + (size_t)nc * 32);
#pragma unroll
    for (int q = 0; q < 8; q++) {
        float4 tq = ar[q];
        const float* w0 = sWu1 + (9 + 4 * q) * 16 + 8 * h;
#pragma unroll
        for (int i = 0; i < 8; i++) {
            float s = u1[i];
            s = fmaf(tq.x, w0[i], s);
            s = fmaf(tq.y, w0[16 + i], s);
            s = fmaf(tq.z, w0[32 + i], s);
            s = fmaf(tq.w, w0[48 + i], s);
            u1[i] = s;
        }
    }
#pragma unroll
    for (int i = 0; i < 8; i++) u1[i] = fmaxf(u1[i], 0.f);

    float u2[8];
#pragma unroll
    for (int j = 0; j < 8; j++) u2[j] = sbu2[j];
#pragma unroll
    for (int i = 0; i < 8; i++) {
        float ui = u1[i];
        const float* w = sWu2 + (8 * h + i) * 8;
#pragma unroll
        for (int j = 0; j < 8; j++) u2[j] = fmaf(ui, w[j], u2[j]);
    }
#pragma unroll
    for (int i = 0; i < 8; i++) {
        float up = __shfl_xor_sync(FULL, u1[i], 1);
        const float* w = sWu2 + (8 * (h ^ 1) + i) * 8;
#pragma unroll
        for (int j = 0; j < 8; j++) u2[j] = fmaf(up, w[j], u2[j]);
    }
#pragma unroll
    for (int j = 0; j < 8; j++) u2[j] = fmaxf(u2[j], 0.f);

    float nx[9];
    nx[0] = xv[0];
#pragma unroll
    for (int j = 0; j < 8; j++) nx[1 + j] = u2[j];
    if (ok && h == 0) {
#pragma unroll
        for (int c = 0; c < 9; c++) g_x[n * 9 + c] = nx[c];
    }

    float p[16];
#pragma unroll
    for (int j = 0; j < 16; j++) p[j] = sbm1[16 * h + j];
#pragma unroll
    for (int c = 0; c < 9; c++) {
        float xc = nx[c];
        const float* w = sWm1 + c * 32 + 16 * h;
#pragma unroll
        for (int j = 0; j < 16; j++) p[j] = fmaf(xc, w[j], p[j]);
    }
    if (ok) {
        float4* Pr = (float4*)(g_P + (size_t)n * 32 + 16 * h);
        float4* Az = (float4*)(g_aggr + (size_t)n * 32 + 16 * h);
        float4 z4 = make_float4(0.f, 0.f, 0.f, 0.f);
#pragma unroll
        for (int q = 0; q < 4; q++) {
            Pr[q] = make_float4(p[4 * q], p[4 * q + 1], p[4 * q + 2], p[4 * q + 3]);
            Az[q] = z4;
        }
    }
}

// ---------------------------------------------------------------------------
// Final round: update MLP fused with h2o head, two threads per node.
// ---------------------------------------------------------------------------
__global__ void __launch_bounds__(128, 8)
final_kernel(const float* __restrict__ Wu1, const float* __restrict__ bu1,
             const float* __restrict__ Wu2, const float* __restrict__ bu2,
             const float* __restrict__ Wh1, const float* __restrict__ bh1,
             const float* __restrict__ Wh2, const float* __restrict__ bh2,
             float* __restrict__ out, int N) {
    __shared__ float sWu1[656], sWu2[128], sWh1[128], sWh2[16];
    __shared__ float sbu1[16], sbu2[8], sbh1[16], sbh2;
    for (int i = threadIdx.x; i < 656; i += blockDim.x) sWu1[i] = Wu1[i];
    for (int i = threadIdx.x; i < 128; i += blockDim.x) sWu2[i] = Wu2[i];
    for (int i = threadIdx.x; i < 128; i += blockDim.x) sWh1[i] = Wh1[i];
    if (threadIdx.x < 16) { sWh2[threadIdx.x] = Wh2[threadIdx.x]; sbu1[threadIdx.x] = bu1[threadIdx.x]; sbh1[threadIdx.x] = bh1[threadIdx.x]; }
    if (threadIdx.x < 8)  sbu2[threadIdx.x] = bu2[threadIdx.x];
    if (threadIdx.x == 0) sbh2 = bh2[0];
    __syncthreads();

    const unsigned FULL = 0xffffffffu;
    int t = blockIdx.x * blockDim.x + threadIdx.x;
    int n = t >> 1, h = t & 1;
    bool ok = n < N;
    int nc = ok ? n : (N - 1);

    float xv[9];
#pragma unroll
    for (int c = 0; c < 9; c++) xv[c] = g_x[nc * 9 + c];

    float u1[8];
#pragma unroll
    for (int i = 0; i < 8; i++) u1[i] = sbu1[8 * h + i];
#pragma unroll
    for (int c = 0; c < 9; c++) {
        float xc = xv[c];
#pragma unroll
        for (int i = 0; i < 8; i++) u1[i] = fmaf(xc, sWu1[c * 16 + 8 * h + i], u1[i]);
    }
    const float4* ar = (const float4*)(g_aggr + (size_t)nc * 32);
#pragma unroll
    for (int q = 0; q < 8; q++) {
        float4 tq = ar[q];
        const float* w0 = sWu1 + (9 + 4 * q) * 16 + 8 * h;
#pragma unroll
        for (int i = 0; i < 8; i++) {
            float s = u1[i];
            s = fmaf(tq.x, w0[i], s);
            s = fmaf(tq.y, w0[16 + i], s);
            s = fmaf(tq.z, w0[32 + i], s);
            s = fmaf(tq.w, w0[48 + i], s);
            u1[i] = s;
        }
    }
#pragma unroll
    for (int i = 0; i < 8; i++) u1[i] = fmaxf(u1[i], 0.f);

    float u2[8];
#pragma unroll
    for (int j = 0; j < 8; j++) u2[j] = sbu2[j];
#pragma unroll
    for (int i = 0; i < 8; i++) {
        float ui = u1[i];
        const float* w = sWu2 + (8 * h + i) * 8;
#pragma unroll
        for (int j = 0; j < 8; j++) u2[j] = fmaf(ui, w[j], u2[j]);
    }
#pragma unroll
    for (int i = 0; i < 8; i++) {
        float up = __shfl_xor_sync(FULL, u1[i], 1);
        const float* w = sWu2 + (8 * (h ^ 1) + i) * 8;
#pragma unroll
        for (int j = 0; j < 8; j++) u2[j] = fmaf(up, w[j], u2[j]);
    }
#pragma unroll
    for (int j = 0; j < 8; j++) u2[j] = fmaxf(u2[j], 0.f);

    float o[8];
#pragma unroll
    for (int i = 0; i < 8; i++) o[i] = sbh1[8 * h + i];
#pragma unroll
    for (int c = 0; c < 8; c++) {
        float uc = u2[c];
#pragma unroll
        for (int i = 0; i < 8; i++) o[i] = fmaf(uc, sWh1[c * 16 + 8 * h + i], o[i]);
    }
    float z = 0.f;
#pragma unroll
    for (int i = 0; i < 8; i++) z = fmaf(fmaxf(o[i], 0.f), sWh2[8 * h + i], z);
    z += __shfl_xor_sync(FULL, z, 1);
    if (ok && h == 0)
        out[n] = 1.f / (1.f + __expf(-(z + sbh2)));
}

// ---------------------------------------------------------------------------
extern "C" void kernel_launch(void* const* d_in, const int* in_sizes, int n_in,
                              void* d_out, int out_size) {
    const float* x   = (const float*)d_in[0];
    const void*  ei  = d_in[1];
    const float* ea  = (const float*)d_in[2];
    const float* Wm1 = (const float*)d_in[3];
    const float* bm1 = (const float*)d_in[4];
    const float* Wm2 = (const float*)d_in[5];
    const float* bm2 = (const float*)d_in[6];
    const float* Wu1 = (const float*)d_in[7];
    const float* bu1 = (const float*)d_in[8];
    const float* Wu2 = (const float*)d_in[9];
    const float* bu2 = (const float*)d_in[10];
    const float* Wh1 = (const float*)d_in[11];
    const float* bh1 = (const float*)d_in[12];
    const float* Wh2 = (const float*)d_in[13];
    const float* bh2 = (const float*)d_in[14];
    float* out = (float*)d_out;

    int N = in_sizes[0] / 9;
    int E = in_sizes[2];  // edge_attr is [E, 1]
    int ngrid = (2 * N + 127) / 128;

    cudaMemcpyToSymbolAsync(cW9, (const char*)Wm1 + 9 * 32 * sizeof(float),
                            32 * sizeof(float), 0, cudaMemcpyDeviceToDevice, 0);
    cudaMemcpyToSymbolAsync(cB2, bm2, 32 * sizeof(float), 0,
                            cudaMemcpyDeviceToDevice, 0);

    init_kernel<<<(N * 32 + 255) / 256, 256>>>(x, Wm1, bm1, Wm2, (const int*)ei, N);
    for (int r = 0; r < 3; r++) {
        edge_kernel<<<(E + 255) / 256, 256>>>(ei, ea, E);
        if (r < 2)
            update_kernel<<<ngrid, 128>>>(Wu1, bu1, Wu2, bu2, Wm1, bm1, N);
        else
            final_kernel<<<ngrid, 128>>>(Wu1, bu1, Wu2, bu2,
                                         Wh1, bh1, Wh2, bh2, out, N);
    }
}